// round 9
// baseline (speedup 1.0000x reference)
#include <cuda_runtime.h>
#include <math.h>
#include <stdint.h>

#define BB 8
#define CIN 96
#define CC 192
#define HH 128
#define WW 128
#define HEADS 8
#define HD 24
#define TT 131072
#define FF 768
#define KCONV 864   // 9*96

// gemm2: block 64x192, 8 warps (2m x 4n), warp 32x48, KT=16, 4 stages
#define ST 4
#define AW (64*16)
#define BW (192*16)
#define STW (AW+BW)          // 4096 words / 16KB per stage
#define G2SMEM (ST*STW*4)    // 65536 B

// ---------------- scratch ----------------
__device__ float g_nx[BB*CIN*HH*WW];
__device__ float g_nv[BB*CIN*HH*WW];
__device__ float g_xp[TT*CC];
__device__ float g_vp[TT*CC];
__device__ float g_xs[TT*CC];
__device__ float g_vs[TT*CC];
__device__ float g_q [TT*CC];
__device__ float g_kv[TT*2*CC];
__device__ float g_at[TT*CC];
__device__ float g_l3[TT*CC];
__device__ float g_h1[(long)TT*FF];
__device__ float g_l4[TT*CC];
// weights: n-major, k-contiguous, k pidx-permuted, tf32-rounded
__device__ float g_qwP [CC*CC];
__device__ float g_kvwP[2*CC*CC];
__device__ float g_apwP[CC*CC];
__device__ float g_f1wP[FF*CC];
__device__ float g_f2wP[CC*FF];
__device__ float g_cqwP[CC*KCONV];
__device__ float g_cvwP[CC*KCONV];

// ---------------- helpers ----------------
__device__ __forceinline__ uint32_t f2tf(float x) {
    uint32_t r; asm("cvt.rna.tf32.f32 %0, %1;" : "=r"(r) : "f"(x)); return r;
}
__device__ __forceinline__ float rnd(float x) { return __uint_as_float(f2tf(x)); }
__device__ __forceinline__ int pidx(int c) {
    return (c & ~7) | ((c & 3) << 1) | ((c >> 2) & 1);
}
__device__ __forceinline__ void mma_tf32(float* d, const uint32_t* a, const uint32_t* b, const float* c) {
    asm("mma.sync.aligned.m16n8k8.row.col.f32.tf32.tf32.f32 "
        "{%0,%1,%2,%3},{%4,%5,%6,%7},{%8,%9},{%10,%11,%12,%13};"
        : "=f"(d[0]), "=f"(d[1]), "=f"(d[2]), "=f"(d[3])
        : "r"(a[0]), "r"(a[1]), "r"(a[2]), "r"(a[3]),
          "r"(b[0]), "r"(b[1]),
          "f"(c[0]), "f"(c[1]), "f"(c[2]), "f"(c[3]));
}
__device__ __forceinline__ void cp16(uint32_t d, const void* s) {
    asm volatile("cp.async.cg.shared.global [%0], [%1], 16;" :: "r"(d), "l"(s));
}
__device__ __forceinline__ void cp16p(uint32_t d, const void* s, int sz) {
    asm volatile("cp.async.cg.shared.global [%0], [%1], 16, %2;" :: "r"(d), "l"(s), "r"(sz));
}
#define CP_COMMIT() asm volatile("cp.async.commit_group;")
#define CP_WAIT2()  asm volatile("cp.async.wait_group 2;")

// ---------------- fused weight prep ----------------
#define S1 (CC*CC)
#define S2 (2*CC*CC)
#define S4 (FF*CC)
#define S6 (KCONV*CC)
__global__ void prep_weights(
    const float* __restrict__ qw, const float* __restrict__ kvw, const float* __restrict__ apw,
    const float* __restrict__ f1w, const float* __restrict__ f2w,
    const float* __restrict__ cqw, const float* __restrict__ cvw,
    float* __restrict__ qwP, float* __restrict__ kvwP, float* __restrict__ apwP,
    float* __restrict__ f1wP, float* __restrict__ f2wP,
    float* __restrict__ cqwP, float* __restrict__ cvwP)
{
    long i = (long)blockIdx.x * 256 + threadIdx.x;
    long o = i;
    if (o < S1) { int n=o/CC, k=o%CC; qwP[(long)n*CC + pidx(k)] = rnd(qw[o]); return; }
    o -= S1;
    if (o < S2) { int n=o/CC, k=o%CC; kvwP[(long)n*CC + pidx(k)] = rnd(kvw[o]); return; }
    o -= S2;
    if (o < S1) { int n=o/CC, k=o%CC; apwP[(long)n*CC + pidx(k)] = rnd(apw[o]); return; }
    o -= S1;
    if (o < S4) { int n=o/CC, k=o%CC; f1wP[(long)n*CC + pidx(k)] = rnd(f1w[o]); return; }
    o -= S4;
    if (o < S4) { int n=o/FF, k=o%FF; f2wP[(long)n*FF + pidx(k)] = rnd(f2w[o]); return; }
    o -= S4;
    if (o < S6) { int oc=o/(CIN*9), rem=o%(CIN*9); int c=rem/9, kk=rem%9;
                  cqwP[(long)oc*KCONV + kk*CIN + pidx(c)] = rnd(cqw[o]); return; }
    o -= S6;
    if (o < S6) { int oc=o/(CIN*9), rem=o%(CIN*9); int c=rem/9, kk=rem%9;
                  cvwP[(long)oc*KCONV + kk*CIN + pidx(c)] = rnd(cvw[o]); return; }
}

// ---------------- NCHW -> NHWC (rounded, c permuted) ----------------
__global__ __launch_bounds__(256) void to_nhwc(const float* __restrict__ in, float* __restrict__ out) {
    __shared__ float tile[32][33];
    int by = blockIdx.z; int b = by >> 7, y = by & 127;
    int c0 = blockIdx.y * 32, x0 = blockIdx.x * 32;
    int tx = threadIdx.x, ty = threadIdx.y;
    #pragma unroll
    for (int i = ty; i < 32; i += 8)
        tile[i][tx] = in[((long)(b * CIN + c0 + i) * HH + y) * WW + x0 + tx];
    __syncthreads();
    #pragma unroll
    for (int i = ty; i < 32; i += 8)
        out[((long)(b * HH + y) * WW + x0 + i) * CIN + pidx(c0 + tx)] = rnd(tile[tx][i]);
}

// ================= tf32 MMA GEMM block 64x192, optional fused LN epilogue =========
// A: [M,K] k-pidx-permuted; W: [N][K] k-pidx-permuted. Out stride = N.
// LN: per-token layernorm over the 192 output cols (requires gridDim.x==1).
template<bool CONV, bool BIAS, bool GELU, bool LNF, bool RAW, bool OPERM, bool ORND>
__global__ __launch_bounds__(256, 3) void gemm2(
    const float* __restrict__ A, const float* __restrict__ W,
    const float* __restrict__ bias, const float* __restrict__ gamma,
    const float* __restrict__ beta, float* __restrict__ Out,
    float* __restrict__ Raw, int N, int K, float alpha)
{
    extern __shared__ float sm_[];
    int tid = threadIdx.x;
    long bm = (long)blockIdx.y * 64;
    int bn = blockIdx.x * 192;
    int wid = tid >> 5, lane = tid & 31;
    int wm = wid >> 2, wn = wid & 3;
    int m0 = wm * 32, n0 = wn * 48;
    int g = lane >> 2, tg = lane & 3;
    int ar = tid >> 2, aseg = tid & 3;
    int asw = aseg ^ (ar & 3);

    uint32_t sB0 = (uint32_t)__cvta_generic_to_shared(sm_);
    uint32_t dA = sB0 + (ar * 16 + asw * 4) * 4;
    uint32_t dB = sB0 + AW * 4 + (ar * 16 + asw * 4) * 4;
    const uint32_t stS = STW * 4;
    const uint32_t rB = 64 * 16 * 4;        // +64 B rows in smem
    const float* pB = W + (long)(bn + ar) * K + aseg * 4;
    const long gB = (long)64 * K;

    const float* pA;
    const float* cbase; int cmask;
    if (CONV) {
        long t = bm + ar;
        int ix = t & 7, iy = (t >> 3) & 7, wx = (t >> 6) & 15, wy = (t >> 10) & 15;
        int b = (int)(t >> 14);
        int xs = wx * 8 + ix, ys = wy * 8 + iy;
        cbase = A + ((long)(b * HH + ys - 1) * WW + (xs - 1)) * CIN;
        int mm = 0;
        #pragma unroll
        for (int ky = 0; ky < 3; ky++)
            #pragma unroll
            for (int kx = 0; kx < 3; kx++) {
                int sy = ys + ky - 1, sx = xs + kx - 1;
                if (sy >= 0 && sy < HH && sx >= 0 && sx < WW) mm |= 1 << (ky * 3 + kx);
            }
        cmask = mm;
    } else {
        pA = A + (bm + ar) * (long)K + aseg * 4;
    }

    int fo0 = (((tg >> 1) ^ (g & 3)) << 2) + ((tg & 1) << 1);
    int fo1 = fo0 ^ 8;

    float acc[2][6][4];
    #pragma unroll
    for (int i = 0; i < 2; i++)
        #pragma unroll
        for (int j = 0; j < 6; j++)
            #pragma unroll
            for (int r = 0; r < 4; r++) acc[i][j][r] = 0.f;

    const int NT = K >> 4;
    // prologue: stages 0..2
    #pragma unroll
    for (int s = 0; s < ST - 1; s++) {
        if (CONV) {
            int tap = s / 6, c0 = (s % 6) * 16;        // s<3 -> tap 0
            bool ok = (cmask >> tap) & 1;
            long doff = ((long)(tap / 3) * WW + (tap % 3)) * CIN + c0 + aseg * 4;
            cp16p(dA + s * stS, ok ? (const void*)(cbase + doff) : (const void*)W, ok ? 16 : 0);
        } else {
            cp16(dA + s * stS, pA + s * 16);
        }
        #pragma unroll
        for (int u = 0; u < 3; u++) cp16(dB + s * stS + u * rB, pB + u * gB + s * 16);
        CP_COMMIT();
    }
    for (int t = 0; t < NT; t++) {
        int buf = t & 3;
        CP_WAIT2();
        __syncthreads();
        int tp = t + 3;
        if (tp < NT) {
            int sb = tp & 3;
            if (CONV) {
                int tap = tp / 6, c0 = (tp - tap * 6) * 16;
                int ky = tap / 3, kx = tap - ky * 3;
                bool ok = (cmask >> tap) & 1;
                long doff = ((long)ky * WW + kx) * CIN + c0 + aseg * 4;
                cp16p(dA + sb * stS, ok ? (const void*)(cbase + doff) : (const void*)W, ok ? 16 : 0);
            } else {
                cp16(dA + sb * stS, pA + tp * 16);
            }
            #pragma unroll
            for (int u = 0; u < 3; u++) cp16(dB + sb * stS + u * rB, pB + u * gB + tp * 16);
        }
        CP_COMMIT();
        const float* as = sm_ + buf * STW;
        const float* bs = sm_ + buf * STW + AW;
        #pragma unroll
        for (int kk = 0; kk < 2; kk++) {
            int fo = kk ? fo1 : fo0;
            uint32_t af[2][4];
            #pragma unroll
            for (int i = 0; i < 2; i++) {
                float2 aLo = *(const float2*)&as[(m0 + i*16 + g)     * 16 + fo];
                float2 aHi = *(const float2*)&as[(m0 + i*16 + g + 8) * 16 + fo];
                af[i][0] = __float_as_uint(aLo.x); af[i][1] = __float_as_uint(aHi.x);
                af[i][2] = __float_as_uint(aLo.y); af[i][3] = __float_as_uint(aHi.y);
            }
            #pragma unroll
            for (int j = 0; j < 6; j++) {
                float2 bv = *(const float2*)&bs[(n0 + j*8 + g) * 16 + fo];
                uint32_t bf[2] = { __float_as_uint(bv.x), __float_as_uint(bv.y) };
                mma_tf32(acc[0][j], af[0], bf, acc[0][j]);
                mma_tf32(acc[1][j], af[1], bf, acc[1][j]);
            }
        }
    }

    // ---- transform (bias/alpha/gelu) in place ----
    #pragma unroll
    for (int i = 0; i < 2; i++)
        #pragma unroll
        for (int j = 0; j < 6; j++)
            #pragma unroll
            for (int r = 0; r < 4; r++) {
                float v = acc[i][j][r];
                if (BIAS) v += __ldg(&bias[bn + n0 + j*8 + 2*tg + (r & 1)]);
                v *= alpha;
                if (GELU) v = 0.5f * v * (1.f + erff(v * 0.70710678118654752f));
                acc[i][j][r] = v;
            }

    if (RAW) {
        #pragma unroll
        for (int i = 0; i < 2; i++)
            #pragma unroll
            for (int j = 0; j < 6; j++)
                #pragma unroll
                for (int hf = 0; hf < 2; hf++) {
                    long row = bm + m0 + i*16 + g + hf*8;
                    int col = bn + n0 + j*8 + 2*tg;
                    *(float2*)&Raw[row * N + col] = make_float2(acc[i][j][hf*2], acc[i][j][hf*2+1]);
                }
    }

    if (LNF) {
        // per-token LN over 192 cols (gridDim.x == 1)
        float mean_[2][2], rstd_[2][2];
        {
            float ps[2][2], pq[2][2];
            #pragma unroll
            for (int i = 0; i < 2; i++)
                #pragma unroll
                for (int hf = 0; hf < 2; hf++) {
                    float s = 0.f, qq = 0.f;
                    #pragma unroll
                    for (int j = 0; j < 6; j++) {
                        float v0 = acc[i][j][hf*2], v1 = acc[i][j][hf*2+1];
                        s += v0 + v1; qq += v0*v0 + v1*v1;
                    }
                    s  += __shfl_xor_sync(~0u, s, 1);  s  += __shfl_xor_sync(~0u, s, 2);
                    qq += __shfl_xor_sync(~0u, qq, 1); qq += __shfl_xor_sync(~0u, qq, 2);
                    ps[i][hf] = s; pq[i][hf] = qq;
                }
            __syncthreads();
            float* red = sm_;                     // [64 rows][4 warps][2]
            if (tg == 0) {
                #pragma unroll
                for (int i = 0; i < 2; i++)
                    #pragma unroll
                    for (int hf = 0; hf < 2; hf++) {
                        int rl = m0 + i*16 + hf*8 + g;
                        red[rl*8 + wn*2 + 0] = ps[i][hf];
                        red[rl*8 + wn*2 + 1] = pq[i][hf];
                    }
            }
            __syncthreads();
            #pragma unroll
            for (int i = 0; i < 2; i++)
                #pragma unroll
                for (int hf = 0; hf < 2; hf++) {
                    int rl = m0 + i*16 + hf*8 + g;
                    float s = red[rl*8+0] + red[rl*8+2] + red[rl*8+4] + red[rl*8+6];
                    float qq = red[rl*8+1] + red[rl*8+3] + red[rl*8+5] + red[rl*8+7];
                    float mn = s * (1.f/192.f);
                    float var = qq * (1.f/192.f) - mn*mn;
                    mean_[i][hf] = mn;
                    rstd_[i][hf] = rsqrtf(var + 1e-5f);
                }
        }
        #pragma unroll
        for (int i = 0; i < 2; i++)
            #pragma unroll
            for (int j = 0; j < 6; j++)
                #pragma unroll
                for (int r = 0; r < 4; r++) {
                    int hf = r >> 1;
                    long row = bm + m0 + i*16 + g + hf*8;
                    int cl = n0 + j*8 + 2*tg + (r & 1);
                    float nv = (acc[i][j][r] - mean_[i][hf]) * rstd_[i][hf] * __ldg(&gamma[cl]) + __ldg(&beta[cl]);
                    if (ORND) nv = rnd(nv);
                    Out[row * 192 + (OPERM ? pidx(cl) : cl)] = nv;
                }
    } else {
        #pragma unroll
        for (int i = 0; i < 2; i++)
            #pragma unroll
            for (int j = 0; j < 6; j++)
                #pragma unroll
                for (int hf = 0; hf < 2; hf++) {
                    long row = bm + m0 + i*16 + g + hf*8;
                    int col = bn + n0 + j*8 + 2*tg;
                    float v0 = acc[i][j][hf*2], v1 = acc[i][j][hf*2+1];
                    if (ORND) { v0 = rnd(v0); v1 = rnd(v1); }
                    if (OPERM) {
                        Out[row * N + pidx(col)]     = v0;
                        Out[row * N + pidx(col + 1)] = v1;
                    } else {
                        *(float2*)&Out[row * N + col] = make_float2(v0, v1);
                    }
                }
    }
}

// ---------------- windowed attention (R8 version, unchanged) ----------------
#define ATQ0 0
#define ATK0 12288
#define ATV0 24576
#define ATRP 36864
__global__ __launch_bounds__(256) void attn_kernel(
    const float* __restrict__ q, const float* __restrict__ kv,
    const float* __restrict__ rpb, float* __restrict__ out)
{
    __shared__ __align__(16) char smem[36864 + 7200];
    uint32_t sb = (uint32_t)__cvta_generic_to_shared(smem);
    float* s_rpb = (float*)(smem + ATRP);
    int w = blockIdx.x;
    int tid = threadIdx.x;
    long tb = (long)w * 64;

    for (int e = tid; e < 225 * 8; e += 256) s_rpb[e] = rpb[e];

    auto loadh = [&](int h, int s) {
        #pragma unroll
        for (int it = 0; it < 2; it++) {
            int idx = tid + it * 256;
            if (idx < 384) {
                int p = idx / 6, d4 = idx - p * 6;
                const float* qg = q  + (tb + p) * CC     + h * HD + d4 * 4;
                const float* kg = kv + (tb + p) * 2 * CC + h * HD + d4 * 4;
                uint32_t off = s * 6144 + idx * 16;
                cp16(sb + ATQ0 + off, qg);
                cp16(sb + ATK0 + off, kg);
                cp16(sb + ATV0 + off, kg + CC);
            }
        }
        CP_COMMIT();
    };
    loadh(0, 0);

    int i = tid >> 2, l = tid & 3;
    int iy = i >> 3, ixx = i & 7;

    for (int h = 0; h < HEADS; h++) {
        int s = h & 1;
        __syncthreads();
        if (h + 1 < HEADS) {
            loadh(h + 1, s ^ 1);
            asm volatile("cp.async.wait_group 1;" ::: "memory");
        } else {
            asm volatile("cp.async.wait_group 0;" ::: "memory");
        }
        __syncthreads();

        const float4* sQ = (const float4*)(smem + s * 6144);
        const float4* sK = (const float4*)(smem + ATK0 + s * 6144);
        const float4* sV = (const float4*)(smem + ATV0 + s * 6144);

        float4 q4[6];
        #pragma unroll
        for (int d4 = 0; d4 < 6; d4++) q4[d4] = sQ[i * 6 + d4];

        float sreg[16];
        #pragma unroll
        for (int jj = 0; jj < 16; jj++) {
            int j = jj * 4 + l;
            float acc = 0.f;
            #pragma unroll
            for (int d4 = 0; d4 < 6; d4++) {
                float4 k4 = sK[j * 6 + d4];
                acc = fmaf(q4[d4].x, k4.x, acc);
                acc = fmaf(q4[d4].y, k4.y, acc);
                acc = fmaf(q4[d4].z, k4.z, acc);
                acc = fmaf(q4[d4].w, k4.w, acc);
            }
            int ry = iy - (j >> 3) + 7;
            int rx = ixx - (j & 7) + 7;
            sreg[jj] = acc + s_rpb[(ry * 15 + rx) * 8 + h];
        }
        float mx = sreg[0];
        #pragma unroll
        for (int jj = 1; jj < 16; jj++) mx = fmaxf(mx, sreg[jj]);
        mx = fmaxf(mx, __shfl_xor_sync(~0u, mx, 1));
        mx = fmaxf(mx, __shfl_xor_sync(~0u, mx, 2));
        float sum = 0.f;
        #pragma unroll
        for (int jj = 0; jj < 16; jj++) { sreg[jj] = __expf(sreg[jj] - mx); sum += sreg[jj]; }
        sum += __shfl_xor_sync(~0u, sum, 1);
        sum += __shfl_xor_sync(~0u, sum, 2);
        float inv = 1.f / sum;

        float oa[24];
        #pragma unroll
        for (int d = 0; d < 24; d++) oa[d] = 0.f;
        #pragma unroll
        for (int jj = 0; jj < 16; jj++) {
            int j = jj * 4 + l;
            float p = sreg[jj] * inv;
            #pragma unroll
            for (int d4 = 0; d4 < 6; d4++) {
                float4 v4 = sV[j * 6 + d4];
                oa[d4*4+0] = fmaf(p, v4.x, oa[d4*4+0]);
                oa[d4*4+1] = fmaf(p, v4.y, oa[d4*4+1]);
                oa[d4*4+2] = fmaf(p, v4.z, oa[d4*4+2]);
                oa[d4*4+3] = fmaf(p, v4.w, oa[d4*4+3]);
            }
        }
        #pragma unroll
        for (int d = 0; d < 24; d++) {
            oa[d] += __shfl_xor_sync(~0u, oa[d], 1);
            oa[d] += __shfl_xor_sync(~0u, oa[d], 2);
        }
        long ob = (tb + i) * CC;
        #pragma unroll
        for (int dd = 0; dd < 6; dd++) {
            int d = l * 6 + dd;
            out[ob + pidx(h * HD + d)] = rnd(oa[d]);
        }
    }
}

// ---------------- token layout -> NCHW with residual ----------------
__global__ __launch_bounds__(256) void final_kernel(
    const float* __restrict__ mln, const float* __restrict__ xp,
    const float* __restrict__ vp, float* __restrict__ out)
{
    __shared__ float s[128][33];
    int bx = blockIdx.x;
    int cch = bx % 6;
    int by = bx / 6;
    int b = by >> 7, y = by & 127;
    int c0 = cch * 32;
    int tid = threadIdx.x;
    int wy = y >> 3, iy = y & 7;
    #pragma unroll
    for (int it = 0; it < 16; it++) {
        int e = tid + it * 256;
        int x = e >> 5, cl = e & 31;
        long t = (long)b * 16384 + (wy * 16 + (x >> 3)) * 64 + iy * 8 + (x & 7);
        long a = t * CC + c0 + cl;
        s[x][cl] = mln[a] + xp[a] + vp[a];
    }
    __syncthreads();
    #pragma unroll
    for (int it = 0; it < 16; it++) {
        int e = tid + it * 256;
        int x = e & 127, c = e >> 7;
        out[((long)(b * CC + c0 + c) * HH + y) * WW + x] = s[x][c];
    }
}

extern "C" void kernel_launch(void* const* d_in, const int* in_sizes, int n_in,
                              void* d_out, int out_size)
{
    const float* x    = (const float*)d_in[0];
    const float* v    = (const float*)d_in[1];
    const float* pq_w = (const float*)d_in[2];
    const float* pq_b = (const float*)d_in[3];
    const float* pv_w = (const float*)d_in[4];
    const float* pv_b = (const float*)d_in[5];
    const float* n1w  = (const float*)d_in[6];
    const float* n1b  = (const float*)d_in[7];
    const float* n2w  = (const float*)d_in[8];
    const float* n2b  = (const float*)d_in[9];
    const float* n3w  = (const float*)d_in[10];
    const float* n3b  = (const float*)d_in[11];
    const float* n4w  = (const float*)d_in[12];
    const float* n4b  = (const float*)d_in[13];
    const float* qw   = (const float*)d_in[14];
    const float* kvw  = (const float*)d_in[15];
    const float* apw  = (const float*)d_in[16];
    const float* apb  = (const float*)d_in[17];
    const float* rpb  = (const float*)d_in[18];
    const float* f1w  = (const float*)d_in[19];
    const float* f1b  = (const float*)d_in[20];
    const float* f2w  = (const float*)d_in[21];
    const float* f2b  = (const float*)d_in[22];
    float* out = (float*)d_out;
    (void)in_sizes; (void)n_in; (void)out_size;

    float *nx,*nv,*xp,*vp,*xs,*vs,*q,*kv,*at,*l3,*h1,*l4;
    float *qwP,*kvwP,*apwP,*f1wP,*f2wP,*cqwP,*cvwP;
    cudaGetSymbolAddress((void**)&nx, g_nx);
    cudaGetSymbolAddress((void**)&nv, g_nv);
    cudaGetSymbolAddress((void**)&xp, g_xp);
    cudaGetSymbolAddress((void**)&vp, g_vp);
    cudaGetSymbolAddress((void**)&xs, g_xs);
    cudaGetSymbolAddress((void**)&vs, g_vs);
    cudaGetSymbolAddress((void**)&q , g_q );
    cudaGetSymbolAddress((void**)&kv, g_kv);
    cudaGetSymbolAddress((void**)&at, g_at);
    cudaGetSymbolAddress((void**)&l3, g_l3);
    cudaGetSymbolAddress((void**)&h1, g_h1);
    cudaGetSymbolAddress((void**)&l4, g_l4);
    cudaGetSymbolAddress((void**)&qwP , g_qwP );
    cudaGetSymbolAddress((void**)&kvwP, g_kvwP);
    cudaGetSymbolAddress((void**)&apwP, g_apwP);
    cudaGetSymbolAddress((void**)&f1wP, g_f1wP);
    cudaGetSymbolAddress((void**)&f2wP, g_f2wP);
    cudaGetSymbolAddress((void**)&cqwP, g_cqwP);
    cudaGetSymbolAddress((void**)&cvwP, g_cvwP);

    const float SCALE = 0.20412414523193154f;  // 24^-0.5

    // gemm2 instantiations
    auto kConv = gemm2<true ,true ,false,true ,true ,true ,true >;
    auto kPlain= gemm2<false,false,false,false,false,false,false>;
    auto kApLn = gemm2<false,true ,false,true ,false,true ,true >;
    auto kFc1  = gemm2<false,true ,true ,false,false,true ,true >;
    auto kFc2Ln= gemm2<false,true ,false,true ,false,false,false>;
    cudaFuncSetAttribute(kConv , cudaFuncAttributeMaxDynamicSharedMemorySize, G2SMEM);
    cudaFuncSetAttribute(kPlain, cudaFuncAttributeMaxDynamicSharedMemorySize, G2SMEM);
    cudaFuncSetAttribute(kApLn , cudaFuncAttributeMaxDynamicSharedMemorySize, G2SMEM);
    cudaFuncSetAttribute(kFc1  , cudaFuncAttributeMaxDynamicSharedMemorySize, G2SMEM);
    cudaFuncSetAttribute(kFc2Ln, cudaFuncAttributeMaxDynamicSharedMemorySize, G2SMEM);

    long totalW = (long)S1 + S2 + S1 + S4 + S4 + S6 + S6;
    prep_weights<<<(int)((totalW + 255) / 256), 256>>>(
        qw, kvw, apw, f1w, f2w, pq_w, pv_w,
        qwP, kvwP, apwP, f1wP, f2wP, cqwP, cvwP);

    to_nhwc<<<dim3(4,3,1024),dim3(32,8)>>>(x, nx);
    to_nhwc<<<dim3(4,3,1024),dim3(32,8)>>>(v, nv);

    // conv + bias + (xp raw, xs = LN1 rounded+perm)
    kConv<<<dim3(1,2048),256,G2SMEM>>>(nx, cqwP, pq_b, n1w, n1b, xs, xp, CC, KCONV, 1.f);
    kConv<<<dim3(1,2048),256,G2SMEM>>>(nv, cvwP, pv_b, n2w, n2b, vs, vp, CC, KCONV, 1.f);

    // q / kv projections (natural layout out)
    kPlain<<<dim3(1,2048),256,G2SMEM>>>(xs, qwP , nullptr, nullptr, nullptr, q , nullptr, CC,   CC, SCALE);
    kPlain<<<dim3(2,2048),256,G2SMEM>>>(vs, kvwP, nullptr, nullptr, nullptr, kv, nullptr, 2*CC, CC, 1.f);

    attn_kernel<<<2048,256>>>(q, kv, rpb, at);

    // attn proj + bias + LN3 (l3 rounded+perm); pr never materialized
    kApLn<<<dim3(1,2048),256,G2SMEM>>>(at, apwP, apb, n3w, n3b, l3, nullptr, CC, CC, 1.f);

    // fc1 + bias + gelu (h1 rounded+perm)
    kFc1<<<dim3(4,2048),256,G2SMEM>>>(l3, f1wP, f1b, nullptr, nullptr, h1, nullptr, FF, CC, 1.f);

    // fc2 + bias, x2 (m=m+m fold), LN4 (l4 natural); m never materialized
    kFc2Ln<<<dim3(1,2048),256,G2SMEM>>>(h1, f2wP, f2b, n4w, n4b, l4, nullptr, CC, FF, 2.f);

    final_kernel<<<6144,256>>>(l4, xp, vp, out);
}

// round 10
// speedup vs baseline: 1.0636x; 1.0636x over previous
#include <cuda_runtime.h>
#include <math.h>
#include <stdint.h>

#define BB 8
#define CIN 96
#define CC 192
#define HH 128
#define WW 128
#define WS 8
#define HEADS 8
#define HD 24
#define TT 131072
#define FF 768
#define KCONV 864   // 9*96

// pipeline
#define ST 5
#define AWORDS (256*16)
#define BWORDS (64*16)
#define SMEMB (ST*(AWORDS+BWORDS)*4)

// ---------------- scratch ----------------
__device__ float g_nx[BB*CIN*HH*WW];
__device__ float g_nv[BB*CIN*HH*WW];
__device__ float g_xp[TT*CC];
__device__ float g_vp[TT*CC];
__device__ float g_xs[TT*CC];
__device__ float g_vs[TT*CC];
__device__ float g_q [TT*CC];
__device__ float g_kv[TT*2*CC];
__device__ float g_at[TT*CC];
__device__ float g_pr[TT*CC];
__device__ float g_l3[TT*CC];
__device__ float g_h1[(long)TT*FF];
__device__ float g_m [TT*CC];
__device__ float g_l4[TT*CC];
// weights: n-major, k-contiguous, k permuted in (k,k+4) pairs, tf32-rounded
__device__ float g_qwP [CC*CC];
__device__ float g_kvwP[2*CC*CC];
__device__ float g_apwP[CC*CC];
__device__ float g_f1wP[FF*CC];
__device__ float g_f2wP[CC*FF];
__device__ float g_cqwP[CC*KCONV];
__device__ float g_cvwP[CC*KCONV];

// ---------------- helpers ----------------
__device__ __forceinline__ uint32_t f2tf(float x) {
    uint32_t r; asm("cvt.rna.tf32.f32 %0, %1;" : "=r"(r) : "f"(x)); return r;
}
__device__ __forceinline__ float rnd(float x) { return __uint_as_float(f2tf(x)); }
__device__ __forceinline__ int pidx(int c) {
    return (c & ~7) | ((c & 3) << 1) | ((c >> 2) & 1);
}

__device__ __forceinline__ void mma_tf32(float* d, const uint32_t* a, const uint32_t* b, const float* c) {
    asm("mma.sync.aligned.m16n8k8.row.col.f32.tf32.tf32.f32 "
        "{%0,%1,%2,%3},{%4,%5,%6,%7},{%8,%9},{%10,%11,%12,%13};"
        : "=f"(d[0]), "=f"(d[1]), "=f"(d[2]), "=f"(d[3])
        : "r"(a[0]), "r"(a[1]), "r"(a[2]), "r"(a[3]),
          "r"(b[0]), "r"(b[1]),
          "f"(c[0]), "f"(c[1]), "f"(c[2]), "f"(c[3]));
}
__device__ __forceinline__ void cp16(uint32_t d, const void* s) {
    asm volatile("cp.async.cg.shared.global [%0], [%1], 16;" :: "r"(d), "l"(s));
}
__device__ __forceinline__ void cp16p(uint32_t d, const void* s, int sz) {
    asm volatile("cp.async.cg.shared.global [%0], [%1], 16, %2;" :: "r"(d), "l"(s), "r"(sz));
}
#define CP_COMMIT() asm volatile("cp.async.commit_group;")
#define CP_WAITN()  asm volatile("cp.async.wait_group 3;")

// ---------------- fused weight prep ----------------
#define S1 (CC*CC)
#define S2 (2*CC*CC)
#define S4 (FF*CC)
#define S6 (KCONV*CC)
__global__ void prep_weights(
    const float* __restrict__ qw, const float* __restrict__ kvw, const float* __restrict__ apw,
    const float* __restrict__ f1w, const float* __restrict__ f2w,
    const float* __restrict__ cqw, const float* __restrict__ cvw,
    float* __restrict__ qwP, float* __restrict__ kvwP, float* __restrict__ apwP,
    float* __restrict__ f1wP, float* __restrict__ f2wP,
    float* __restrict__ cqwP, float* __restrict__ cvwP)
{
    long i = (long)blockIdx.x * 256 + threadIdx.x;
    long o = i;
    if (o < S1) { int n=o/CC, k=o%CC; qwP[(long)n*CC + pidx(k)] = rnd(qw[o]); return; }
    o -= S1;
    if (o < S2) { int n=o/CC, k=o%CC; kvwP[(long)n*CC + pidx(k)] = rnd(kvw[o]); return; }
    o -= S2;
    if (o < S1) { int n=o/CC, k=o%CC; apwP[(long)n*CC + pidx(k)] = rnd(apw[o]); return; }
    o -= S1;
    if (o < S4) { int n=o/CC, k=o%CC; f1wP[(long)n*CC + pidx(k)] = rnd(f1w[o]); return; }
    o -= S4;
    if (o < S4) { int n=o/FF, k=o%FF; f2wP[(long)n*FF + pidx(k)] = rnd(f2w[o]); return; }
    o -= S4;
    if (o < S6) { int oc=o/(CIN*9), rem=o%(CIN*9); int c=rem/9, kk=rem%9;
                  cqwP[(long)oc*KCONV + kk*CIN + pidx(c)] = rnd(cqw[o]); return; }
    o -= S6;
    if (o < S6) { int oc=o/(CIN*9), rem=o%(CIN*9); int c=rem/9, kk=rem%9;
                  cvwP[(long)oc*KCONV + kk*CIN + pidx(c)] = rnd(cvw[o]); return; }
}

// ---------------- NCHW -> NHWC (rounded, c permuted) ----------------
__global__ __launch_bounds__(256) void to_nhwc(const float* __restrict__ in, float* __restrict__ out) {
    __shared__ float tile[32][33];
    int by = blockIdx.z; int b = by >> 7, y = by & 127;
    int c0 = blockIdx.y * 32, x0 = blockIdx.x * 32;
    int tx = threadIdx.x, ty = threadIdx.y;
    #pragma unroll
    for (int i = ty; i < 32; i += 8)
        tile[i][tx] = in[((long)(b * CIN + c0 + i) * HH + y) * WW + x0 + tx];
    __syncthreads();
    #pragma unroll
    for (int i = ty; i < 32; i += 8)
        out[((long)(b * HH + y) * WW + x0 + i) * CIN + pidx(c0 + tx)] = rnd(tile[tx][i]);
}

// ================= tf32 MMA GEMM: block 256x64, warp 64x32, 5-stage pipeline ======
template<bool BIAS, bool GELU, bool ROUND, bool PERMW>
__global__ __launch_bounds__(256, 2) void mm_tf32(
    const float* __restrict__ A, const float* __restrict__ W,
    const float* __restrict__ bias, float* __restrict__ C,
    int M, int N, int K, float alpha)
{
    extern __shared__ float sm_[];
    float* As = sm_;
    float* Bs = sm_ + ST * AWORDS;
    int tid = threadIdx.x;
    long bm = (long)blockIdx.y * 256;
    int bn = blockIdx.x * 64;
    int wid = tid >> 5, lane = tid & 31;
    int wm = wid >> 1, wn = wid & 1;
    int m0 = wm * 64, n0 = wn * 32;
    int g = lane >> 2, tg = lane & 3;

    int ar = tid >> 2, aseg = tid & 3;
    int asw = aseg ^ (ar & 3);

    uint32_t sAa = (uint32_t)__cvta_generic_to_shared(As);
    uint32_t sBa = (uint32_t)__cvta_generic_to_shared(Bs);
    uint32_t dA = sAa + (ar * 16 + asw * 4) * 4;
    uint32_t dB = sBa + (ar * 16 + asw * 4) * 4;
    const float* pA = A + (bm + ar) * K + aseg * 4;
    const float* pB = W + (long)(bn + ar) * K + aseg * 4;
    const uint32_t stA = AWORDS * 4, stB = BWORDS * 4;
    const uint32_t rA = 64 * 16 * 4;
    const long     gA = (long)64 * K;

    int fo0 = (((tg >> 1) ^ (g & 3)) << 2) + ((tg & 1) << 1);
    int fo1 = fo0 ^ 8;

    float acc[4][4][4];
    #pragma unroll
    for (int i = 0; i < 4; i++)
        #pragma unroll
        for (int j = 0; j < 4; j++)
            #pragma unroll
            for (int r = 0; r < 4; r++) acc[i][j][r] = 0.f;

    int NT = K / 16;
    #pragma unroll
    for (int s = 0; s < ST - 1; s++) {
        if (s < NT) {
            #pragma unroll
            for (int h = 0; h < 4; h++) cp16(dA + s * stA + h * rA, pA + s * 16 + h * gA);
            cp16(dB + s * stB, pB + s * 16);
        }
        CP_COMMIT();
    }
    for (int t = 0; t < NT; t++) {
        int buf = t % ST;
        CP_WAITN();
        __syncthreads();
        int tp = t + ST - 1;
        if (tp < NT) {
            int sb = tp % ST;
            #pragma unroll
            for (int h = 0; h < 4; h++) cp16(dA + sb * stA + h * rA, pA + tp * 16 + h * gA);
            cp16(dB + sb * stB, pB + tp * 16);
        }
        CP_COMMIT();
        const float* as = As + buf * AWORDS;
        const float* bs = Bs + buf * BWORDS;
        #pragma unroll
        for (int kk = 0; kk < 2; kk++) {
            int fo = kk ? fo1 : fo0;
            uint32_t af[4][4];
            #pragma unroll
            for (int i = 0; i < 4; i++) {
                float2 aLo = *(const float2*)&as[(m0 + i*16 + g)     * 16 + fo];
                float2 aHi = *(const float2*)&as[(m0 + i*16 + g + 8) * 16 + fo];
                af[i][0] = __float_as_uint(aLo.x); af[i][1] = __float_as_uint(aHi.x);
                af[i][2] = __float_as_uint(aLo.y); af[i][3] = __float_as_uint(aHi.y);
            }
            #pragma unroll
            for (int j = 0; j < 4; j++) {
                float2 bv = *(const float2*)&bs[(n0 + j*8 + g) * 16 + fo];
                uint32_t bf[2] = { __float_as_uint(bv.x), __float_as_uint(bv.y) };
                #pragma unroll
                for (int i = 0; i < 4; i++)
                    mma_tf32(acc[i][j], af[i], bf, acc[i][j]);
            }
        }
    }
    #pragma unroll
    for (int i = 0; i < 4; i++) {
        long row0 = bm + m0 + i * 16 + g;
        #pragma unroll
        for (int j = 0; j < 4; j++) {
            int col = bn + n0 + j * 8 + 2 * tg;
            float b0 = 0.f, b1 = 0.f;
            if (BIAS) { b0 = bias[col]; b1 = bias[col + 1]; }
            #pragma unroll
            for (int half = 0; half < 2; half++) {
                long row = row0 + half * 8;
                float v0 = (acc[i][j][half * 2 + 0] + b0) * alpha;
                float v1 = (acc[i][j][half * 2 + 1] + b1) * alpha;
                if (GELU) {
                    v0 = 0.5f * v0 * (1.f + erff(v0 * 0.70710678118654752f));
                    v1 = 0.5f * v1 * (1.f + erff(v1 * 0.70710678118654752f));
                }
                if (ROUND) { v0 = rnd(v0); v1 = rnd(v1); }
                if (PERMW) {
                    C[row * N + pidx(col)]     = v0;
                    C[row * N + pidx(col + 1)] = v1;
                } else {
                    *(float2*)&C[row * N + col] = make_float2(v0, v1);
                }
            }
        }
    }
}

// ================= conv3x3 implicit GEMM: 256x64, 5-stage pipeline =================
__global__ __launch_bounds__(256, 2) void conv_tf32(
    const float* __restrict__ nhwc, const float* __restrict__ W,
    const float* __restrict__ bias, float* __restrict__ C)
{
    extern __shared__ float sm_[];
    float* As = sm_;
    float* Bs = sm_ + ST * AWORDS;
    const int N = CC;
    int tid = threadIdx.x;
    long bm = (long)blockIdx.y * 256;
    int bn = blockIdx.x * 64;
    int wid = tid >> 5, lane = tid & 31;
    int wm = wid >> 1, wn = wid & 1;
    int m0 = wm * 64, n0 = wn * 32;
    int g = lane >> 2, tg = lane & 3;

    int ar = tid >> 2, aseg = tid & 3;
    int asw = aseg ^ (ar & 3);

    uint32_t sAa = (uint32_t)__cvta_generic_to_shared(As);
    uint32_t sBa = (uint32_t)__cvta_generic_to_shared(Bs);
    uint32_t dA = sAa + (ar * 16 + asw * 4) * 4;
    uint32_t dB = sBa + (ar * 16 + asw * 4) * 4;
    const float* pB = W + (long)(bn + ar) * KCONV + aseg * 4;
    const uint32_t stA = AWORDS * 4, stB = BWORDS * 4;
    const uint32_t rA = 64 * 16 * 4;

    int fo0 = (((tg >> 1) ^ (g & 3)) << 2) + ((tg & 1) << 1);
    int fo1 = fo0 ^ 8;

    const float* base[4];
    int okb[4];
    #pragma unroll
    for (int h = 0; h < 4; h++) {
        long t = bm + ar + h * 64;
        int ix = t & 7, iy = (t >> 3) & 7, wx = (t >> 6) & 15, wy = (t >> 10) & 15;
        int b = (int)(t >> 14);
        int xs = wx * 8 + ix, ys = wy * 8 + iy;
        base[h] = nhwc + ((long)(b * HH + ys - 1) * WW + (xs - 1)) * CIN;
        int m = 0;
        #pragma unroll
        for (int ky = 0; ky < 3; ky++)
            #pragma unroll
            for (int kx = 0; kx < 3; kx++) {
                int sy = ys + ky - 1, sx = xs + kx - 1;
                if (sy >= 0 && sy < HH && sx >= 0 && sx < WW) m |= 1 << (ky * 3 + kx);
            }
        okb[h] = m;
    }

    float acc[4][4][4];
    #pragma unroll
    for (int i = 0; i < 4; i++)
        #pragma unroll
        for (int j = 0; j < 4; j++)
            #pragma unroll
            for (int r = 0; r < 4; r++) acc[i][j][r] = 0.f;

    const int NT = KCONV / 16;   // 54
    #pragma unroll
    for (int s = 0; s < ST - 1; s++) {
        int idx = s / 6, c0 = (s % 6) * 16;   // s<6 -> tap 0
        int ky = idx / 3, kx = idx % 3;
        long doff = (long)ky * (WW * CIN) + kx * CIN + c0 + aseg * 4;
        #pragma unroll
        for (int h = 0; h < 4; h++) {
            bool ok = (okb[h] >> idx) & 1;
            const float* src = ok ? base[h] + doff : nhwc;
            cp16p(dA + s * stA + h * rA, src, ok ? 16 : 0);
        }
        cp16(dB + s * stB, pB + s * 16);
        CP_COMMIT();
    }
    for (int t = 0; t < NT; t++) {
        int buf = t % ST;
        CP_WAITN();
        __syncthreads();
        int tp = t + ST - 1;
        if (tp < NT) {
            int sb = tp % ST;
            int kt = tp * 16;
            int idx = kt / 96, c0 = kt - idx * 96;
            int ky = idx / 3, kx = idx - ky * 3;
            long doff = (long)ky * (WW * CIN) + kx * CIN + c0 + aseg * 4;
            #pragma unroll
            for (int h = 0; h < 4; h++) {
                bool ok = (okb[h] >> idx) & 1;
                const float* src = ok ? base[h] + doff : nhwc;
                cp16p(dA + sb * stA + h * rA, src, ok ? 16 : 0);
            }
            cp16(dB + sb * stB, pB + kt);
        }
        CP_COMMIT();
        const float* as = As + buf * AWORDS;
        const float* bs = Bs + buf * BWORDS;
        #pragma unroll
        for (int kk = 0; kk < 2; kk++) {
            int fo = kk ? fo1 : fo0;
            uint32_t af[4][4];
            #pragma unroll
            for (int i = 0; i < 4; i++) {
                float2 aLo = *(const float2*)&as[(m0 + i*16 + g)     * 16 + fo];
                float2 aHi = *(const float2*)&as[(m0 + i*16 + g + 8) * 16 + fo];
                af[i][0] = __float_as_uint(aLo.x); af[i][1] = __float_as_uint(aHi.x);
                af[i][2] = __float_as_uint(aLo.y); af[i][3] = __float_as_uint(aHi.y);
            }
            #pragma unroll
            for (int j = 0; j < 4; j++) {
                float2 bv = *(const float2*)&bs[(n0 + j*8 + g) * 16 + fo];
                uint32_t bf[2] = { __float_as_uint(bv.x), __float_as_uint(bv.y) };
                #pragma unroll
                for (int i = 0; i < 4; i++)
                    mma_tf32(acc[i][j], af[i], bf, acc[i][j]);
            }
        }
    }
    #pragma unroll
    for (int i = 0; i < 4; i++) {
        long row0 = bm + m0 + i * 16 + g;
        #pragma unroll
        for (int j = 0; j < 4; j++) {
            int col = bn + n0 + j * 8 + 2 * tg;
            float b0 = bias[col], b1 = bias[col + 1];
            #pragma unroll
            for (int half = 0; half < 2; half++) {
                long row = row0 + half * 8;
                *(float2*)&C[row * N + col] =
                    make_float2(acc[i][j][half*2+0] + b0, acc[i][j][half*2+1] + b1);
            }
        }
    }
}

// ---------------- windowed attention: vectorized, register scores ----------------
#define ATQ0 0
#define ATK0 12288
#define ATV0 24576
#define ATRP 36864
__global__ __launch_bounds__(256) void attn_kernel(
    const float* __restrict__ q, const float* __restrict__ kv,
    const float* __restrict__ rpb, float* __restrict__ out)
{
    __shared__ __align__(16) char smem[36864 + 7200];
    uint32_t sb = (uint32_t)__cvta_generic_to_shared(smem);
    float* s_rpb = (float*)(smem + ATRP);
    int w = blockIdx.x;
    int tid = threadIdx.x;
    long tb = (long)w * 64;

    for (int e = tid; e < 225 * 8; e += 256) s_rpb[e] = rpb[e];

    auto loadh = [&](int h, int s) {
        #pragma unroll
        for (int it = 0; it < 2; it++) {
            int idx = tid + it * 256;
            if (idx < 384) {
                int p = idx / 6, d4 = idx - p * 6;
                const float* qg = q  + (tb + p) * CC     + h * HD + d4 * 4;
                const float* kg = kv + (tb + p) * 2 * CC + h * HD + d4 * 4;
                uint32_t off = s * 6144 + idx * 16;
                cp16(sb + ATQ0 + off, qg);
                cp16(sb + ATK0 + off, kg);
                cp16(sb + ATV0 + off, kg + CC);
            }
        }
        CP_COMMIT();
    };
    loadh(0, 0);

    int i = tid >> 2, l = tid & 3;
    int iy = i >> 3, ixx = i & 7;

    for (int h = 0; h < HEADS; h++) {
        int s = h & 1;
        __syncthreads();
        if (h + 1 < HEADS) {
            loadh(h + 1, s ^ 1);
            asm volatile("cp.async.wait_group 1;" ::: "memory");
        } else {
            asm volatile("cp.async.wait_group 0;" ::: "memory");
        }
        __syncthreads();

        const float4* sQ = (const float4*)(smem + s * 6144);
        const float4* sK = (const float4*)(smem + ATK0 + s * 6144);
        const float4* sV = (const float4*)(smem + ATV0 + s * 6144);

        float4 q4[6];
        #pragma unroll
        for (int d4 = 0; d4 < 6; d4++) q4[d4] = sQ[i * 6 + d4];

        float sreg[16];
        #pragma unroll
        for (int jj = 0; jj < 16; jj++) {
            int j = jj * 4 + l;
            float acc = 0.f;
            #pragma unroll
            for (int d4 = 0; d4 < 6; d4++) {
                float4 k4 = sK[j * 6 + d4];
                acc = fmaf(q4[d4].x, k4.x, acc);
                acc = fmaf(q4[d4].y, k4.y, acc);
                acc = fmaf(q4[d4].z, k4.z, acc);
                acc = fmaf(q4[d4].w, k4.w, acc);
            }
            int ry = iy - (j >> 3) + 7;
            int rx = ixx - (j & 7) + 7;
            sreg[jj] = acc + s_rpb[(ry * 15 + rx) * 8 + h];
        }
        float mx = sreg[0];
        #pragma unroll
        for (int jj = 1; jj < 16; jj++) mx = fmaxf(mx, sreg[jj]);
        mx = fmaxf(mx, __shfl_xor_sync(~0u, mx, 1));
        mx = fmaxf(mx, __shfl_xor_sync(~0u, mx, 2));
        float sum = 0.f;
        #pragma unroll
        for (int jj = 0; jj < 16; jj++) { sreg[jj] = __expf(sreg[jj] - mx); sum += sreg[jj]; }
        sum += __shfl_xor_sync(~0u, sum, 1);
        sum += __shfl_xor_sync(~0u, sum, 2);
        float inv = 1.f / sum;

        float oa[24];
        #pragma unroll
        for (int d = 0; d < 24; d++) oa[d] = 0.f;
        #pragma unroll
        for (int jj = 0; jj < 16; jj++) {
            int j = jj * 4 + l;
            float p = sreg[jj] * inv;
            #pragma unroll
            for (int d4 = 0; d4 < 6; d4++) {
                float4 v4 = sV[j * 6 + d4];
                oa[d4*4+0] = fmaf(p, v4.x, oa[d4*4+0]);
                oa[d4*4+1] = fmaf(p, v4.y, oa[d4*4+1]);
                oa[d4*4+2] = fmaf(p, v4.z, oa[d4*4+2]);
                oa[d4*4+3] = fmaf(p, v4.w, oa[d4*4+3]);
            }
        }
        #pragma unroll
        for (int d = 0; d < 24; d++) {
            oa[d] += __shfl_xor_sync(~0u, oa[d], 1);
            oa[d] += __shfl_xor_sync(~0u, oa[d], 2);
        }
        long ob = (tb + i) * CC;
        #pragma unroll
        for (int dd = 0; dd < 6; dd++) {
            int d = l * 6 + dd;
            out[ob + pidx(h * HD + d)] = rnd(oa[d]);
        }
    }
}

// ---------------- row LN ----------------
template<bool ROUND, bool PERM>
__global__ __launch_bounds__(256) void ln_rows_kernel(
    const float* __restrict__ in, const float* __restrict__ gamma,
    const float* __restrict__ beta, float* __restrict__ out)
{
    int warp = threadIdx.x >> 5, lane = threadIdx.x & 31;
    long row = (long)blockIdx.x * 8 + warp;
    const float* p = in + row * CC;
    float v[6];
    float sum = 0.f, sq = 0.f;
    #pragma unroll
    for (int k = 0; k < 6; k++) { v[k] = p[lane + k * 32]; sum += v[k]; sq += v[k] * v[k]; }
    #pragma unroll
    for (int o = 16; o > 0; o >>= 1) { sum += __shfl_xor_sync(~0u, sum, o); sq += __shfl_xor_sync(~0u, sq, o); }
    float mean = sum * (1.f / CC), var = sq * (1.f / CC) - mean * mean;
    float rstd = rsqrtf(var + 1e-5f);
    float* qo = out + row * CC;
    #pragma unroll
    for (int k = 0; k < 6; k++) {
        int c = lane + k * 32;
        float r = (v[k] - mean) * rstd * gamma[c] + beta[c];
        if (ROUND) r = rnd(r);
        qo[PERM ? pidx(c) : c] = r;
    }
}

// dual-tensor LN (LN1 + LN2 in one launch; round+perm)
__global__ __launch_bounds__(256) void ln_rows2_kernel(
    const float* __restrict__ in1, const float* __restrict__ g1, const float* __restrict__ b1,
    float* __restrict__ out1,
    const float* __restrict__ in2, const float* __restrict__ g2, const float* __restrict__ b2,
    float* __restrict__ out2)
{
    int warp = threadIdx.x >> 5, lane = threadIdx.x & 31;
    long gr = (long)blockIdx.x * 8 + warp;
    bool second = gr >= TT;
    long row = second ? gr - TT : gr;
    const float* p = (second ? in2 : in1) + row * CC;
    const float* gamma = second ? g2 : g1;
    const float* beta  = second ? b2 : b1;
    float* qo = (second ? out2 : out1) + row * CC;
    float v[6];
    float sum = 0.f, sq = 0.f;
    #pragma unroll
    for (int k = 0; k < 6; k++) { v[k] = p[lane + k * 32]; sum += v[k]; sq += v[k] * v[k]; }
    #pragma unroll
    for (int o = 16; o > 0; o >>= 1) { sum += __shfl_xor_sync(~0u, sum, o); sq += __shfl_xor_sync(~0u, sq, o); }
    float mean = sum * (1.f / CC), var = sq * (1.f / CC) - mean * mean;
    float rstd = rsqrtf(var + 1e-5f);
    #pragma unroll
    for (int k = 0; k < 6; k++) {
        int c = lane + k * 32;
        float r = rnd((v[k] - mean) * rstd * gamma[c] + beta[c]);
        qo[pidx(c)] = r;
    }
}

// ---------------- token layout -> NCHW with residual ----------------
__global__ __launch_bounds__(256) void final_kernel(
    const float* __restrict__ mln, const float* __restrict__ xp,
    const float* __restrict__ vp, float* __restrict__ out)
{
    __shared__ float s[128][33];
    int bx = blockIdx.x;
    int cch = bx % 6;
    int by = bx / 6;
    int b = by >> 7, y = by & 127;
    int c0 = cch * 32;
    int tid = threadIdx.x;
    int wy = y >> 3, iy = y & 7;
    #pragma unroll
    for (int it = 0; it < 16; it++) {
        int e = tid + it * 256;
        int x = e >> 5, cl = e & 31;
        long t = (long)b * 16384 + (wy * 16 + (x >> 3)) * 64 + iy * 8 + (x & 7);
        long a = t * CC + c0 + cl;
        s[x][cl] = mln[a] + xp[a] + vp[a];
    }
    __syncthreads();
    #pragma unroll
    for (int it = 0; it < 16; it++) {
        int e = tid + it * 256;
        int x = e & 127, c = e >> 7;
        out[((long)(b * CC + c0 + c) * HH + y) * WW + x] = s[x][c];
    }
}

extern "C" void kernel_launch(void* const* d_in, const int* in_sizes, int n_in,
                              void* d_out, int out_size)
{
    const float* x    = (const float*)d_in[0];
    const float* v    = (const float*)d_in[1];
    const float* pq_w = (const float*)d_in[2];
    const float* pq_b = (const float*)d_in[3];
    const float* pv_w = (const float*)d_in[4];
    const float* pv_b = (const float*)d_in[5];
    const float* n1w  = (const float*)d_in[6];
    const float* n1b  = (const float*)d_in[7];
    const float* n2w  = (const float*)d_in[8];
    const float* n2b  = (const float*)d_in[9];
    const float* n3w  = (const float*)d_in[10];
    const float* n3b  = (const float*)d_in[11];
    const float* n4w  = (const float*)d_in[12];
    const float* n4b  = (const float*)d_in[13];
    const float* qw   = (const float*)d_in[14];
    const float* kvw  = (const float*)d_in[15];
    const float* apw  = (const float*)d_in[16];
    const float* apb  = (const float*)d_in[17];
    const float* rpb  = (const float*)d_in[18];
    const float* f1w  = (const float*)d_in[19];
    const float* f1b  = (const float*)d_in[20];
    const float* f2w  = (const float*)d_in[21];
    const float* f2b  = (const float*)d_in[22];
    float* out = (float*)d_out;
    (void)in_sizes; (void)n_in; (void)out_size;

    float *nx,*nv,*xp,*vp,*xs,*vs,*q,*kv,*at,*pr,*l3,*h1,*m,*l4;
    float *qwP,*kvwP,*apwP,*f1wP,*f2wP,*cqwP,*cvwP;
    cudaGetSymbolAddress((void**)&nx, g_nx);
    cudaGetSymbolAddress((void**)&nv, g_nv);
    cudaGetSymbolAddress((void**)&xp, g_xp);
    cudaGetSymbolAddress((void**)&vp, g_vp);
    cudaGetSymbolAddress((void**)&xs, g_xs);
    cudaGetSymbolAddress((void**)&vs, g_vs);
    cudaGetSymbolAddress((void**)&q , g_q );
    cudaGetSymbolAddress((void**)&kv, g_kv);
    cudaGetSymbolAddress((void**)&at, g_at);
    cudaGetSymbolAddress((void**)&pr, g_pr);
    cudaGetSymbolAddress((void**)&l3, g_l3);
    cudaGetSymbolAddress((void**)&h1, g_h1);
    cudaGetSymbolAddress((void**)&m , g_m );
    cudaGetSymbolAddress((void**)&l4, g_l4);
    cudaGetSymbolAddress((void**)&qwP , g_qwP );
    cudaGetSymbolAddress((void**)&kvwP, g_kvwP);
    cudaGetSymbolAddress((void**)&apwP, g_apwP);
    cudaGetSymbolAddress((void**)&f1wP, g_f1wP);
    cudaGetSymbolAddress((void**)&f2wP, g_f2wP);
    cudaGetSymbolAddress((void**)&cqwP, g_cqwP);
    cudaGetSymbolAddress((void**)&cvwP, g_cvwP);

    const float SCALE = 0.20412414523193154f;  // 24^-0.5

    cudaFuncSetAttribute(mm_tf32<false,false,false,false>, cudaFuncAttributeMaxDynamicSharedMemorySize, SMEMB);
    cudaFuncSetAttribute(mm_tf32<true ,false,false,false>, cudaFuncAttributeMaxDynamicSharedMemorySize, SMEMB);
    cudaFuncSetAttribute(mm_tf32<true ,true ,true ,true >, cudaFuncAttributeMaxDynamicSharedMemorySize, SMEMB);
    cudaFuncSetAttribute(conv_tf32, cudaFuncAttributeMaxDynamicSharedMemorySize, SMEMB);

    long totalW = (long)S1 + S2 + S1 + S4 + S4 + S6 + S6;
    prep_weights<<<(int)((totalW + 255) / 256), 256>>>(
        qw, kvw, apw, f1w, f2w, pq_w, pv_w,
        qwP, kvwP, apwP, f1wP, f2wP, cqwP, cvwP);

    to_nhwc<<<dim3(4,3,1024),dim3(32,8)>>>(x, nx);
    to_nhwc<<<dim3(4,3,1024),dim3(32,8)>>>(v, nv);

    conv_tf32<<<dim3(3,512),256,SMEMB>>>(nx, cqwP, pq_b, xp);
    conv_tf32<<<dim3(3,512),256,SMEMB>>>(nv, cvwP, pv_b, vp);

    ln_rows2_kernel<<<32768,256>>>(xp, n1w, n1b, xs, vp, n2w, n2b, vs);

    mm_tf32<false,false,false,false><<<dim3(3,512),256,SMEMB>>>(xs, qwP , nullptr, q , TT, CC,   CC, SCALE);
    mm_tf32<false,false,false,false><<<dim3(6,512),256,SMEMB>>>(vs, kvwP, nullptr, kv, TT, 2*CC, CC, 1.f);

    attn_kernel<<<2048,256>>>(q, kv, rpb, at);

    mm_tf32<true,false,false,false><<<dim3(3,512),256,SMEMB>>>(at, apwP, apb, pr, TT, CC, CC, 1.f);

    ln_rows_kernel<true,true><<<16384,256>>>(pr, n3w, n3b, l3);

    mm_tf32<true,true ,true ,true ><<<dim3(12,512),256,SMEMB>>>(l3, f1wP, f1b, h1, TT, FF, CC, 1.f);
    mm_tf32<true,false,false,false><<<dim3(3,512),256,SMEMB>>>(h1, f2wP, f2b, m , TT, CC, FF, 2.f);

    ln_rows_kernel<false,false><<<16384,256>>>(m, n4w, n4b, l4);

    final_kernel<<<6144,256>>>(l4, xp, vp, out);
}